// round 1
// baseline (speedup 1.0000x reference)
#include <cuda_runtime.h>
#include <math.h>
#include <stdint.h>

// Problem constants (fixed shapes for this problem)
#define NMAX 50000
#define EMAX 800000
#define CDIM 128

// ---------------- device scratch (no allocations allowed) ----------------
__device__ int   g_is64;
__device__ float g_h1 [(size_t)NMAX * CDIM];
__device__ float g_xf [(size_t)NMAX * CDIM];
__device__ float g_agg[(size_t)NMAX * CDIM];
__device__ float g_t  [(size_t)NMAX * CDIM];
__device__ float g_delta[(size_t)NMAX * 3];
__device__ int   g_src [EMAX];
__device__ int   g_dst [EMAX];
__device__ int   g_esrc[EMAX];     // src node id per edge, grouped by dst (CSR payload)
__device__ int   g_cnt [NMAX];
__device__ int   g_cur [NMAX];
__device__ int   g_off [NMAX + 1];

// ---------------- dtype detection for edge_index (int64 vs int32) ----------------
__global__ void detect_kernel(const unsigned int* __restrict__ w, int E) {
    // If data is int64 (values in [0, 50000), nonnegative), every high 32-bit word is 0.
    // If int32, odd words are random indices — virtually certainly not all zero.
    int nz = 0;
    int lim = 2 * E; // words available if int32; int64 has 4E words so also safe
    for (int i = threadIdx.x; i < 256; i += 32) {
        int wi = 2 * i + 1;
        if (wi < lim) nz |= (w[wi] != 0u);
    }
    nz = __any_sync(0xffffffffu, nz);
    if (threadIdx.x == 0) g_is64 = nz ? 0 : 1;
}

__global__ void zero_cnt_kernel(int n) {
    int i = blockIdx.x * blockDim.x + threadIdx.x;
    if (i < n) { g_cnt[i] = 0; g_cur[i] = 0; }
}

// convert edge_index to int32 src/dst and histogram dst
__global__ void convert_hist_kernel(const void* __restrict__ ei, int E) {
    int i = blockIdx.x * blockDim.x + threadIdx.x;
    if (i >= E) return;
    int s, d;
    if (g_is64) {
        const long long* p = (const long long*)ei;
        s = (int)p[i];
        d = (int)p[E + i];
    } else {
        const int* p = (const int*)ei;
        s = p[i];
        d = p[E + i];
    }
    g_src[i] = s;
    g_dst[i] = d;
    atomicAdd(&g_cnt[d], 1);
}

// single-block exclusive scan of g_cnt -> g_off (n up to NMAX)
__global__ void scan_kernel(int n) {
    __shared__ int wsum[32];
    __shared__ int carry;
    int tid = threadIdx.x, lane = tid & 31, wid = tid >> 5;
    if (tid == 0) { carry = 0; g_off[0] = 0; }
    __syncthreads();
    for (int base = 0; base < n; base += 1024) {
        int i = base + tid;
        int v = (i < n) ? g_cnt[i] : 0;
        int x = v;
        #pragma unroll
        for (int d = 1; d < 32; d <<= 1) {
            int t = __shfl_up_sync(0xffffffffu, x, d);
            if (lane >= d) x += t;
        }
        if (lane == 31) wsum[wid] = x;
        __syncthreads();
        if (wid == 0) {
            int s = wsum[lane];
            #pragma unroll
            for (int d = 1; d < 32; d <<= 1) {
                int t = __shfl_up_sync(0xffffffffu, s, d);
                if (lane >= d) s += t;
            }
            wsum[lane] = s;
        }
        __syncthreads();
        int add = carry + (wid ? wsum[wid - 1] : 0);
        if (i < n) g_off[i + 1] = x + add;
        int total = wsum[31];
        __syncthreads();
        if (tid == 0) carry += total;
        __syncthreads();
    }
}

// scatter src values into CSR slots grouped by dst (order within group irrelevant: max is commutative)
__global__ void scatter_kernel(int E) {
    int i = blockIdx.x * blockDim.x + threadIdx.x;
    if (i >= E) return;
    int d = g_dst[i];
    int p = g_off[d] + atomicAdd(&g_cur[d], 1);
    g_esrc[p] = g_src[i];
}

// ---------------- SGEMM: out[M,128] = A[M,128] @ B[128,128] (+bias, +act, +residual) ----------------
// MODE 0: bias only; MODE 1: bias + leaky_relu; MODE 2: bias + residual add
template <int MODE>
__global__ __launch_bounds__(256, 2)
void gemm128_kernel(const float* __restrict__ A, const float* __restrict__ B,
                    const float* __restrict__ bias, const float* __restrict__ R,
                    float* __restrict__ O, int M) {
    extern __shared__ float smem[];
    float* Bs = smem;               // [128 k][128 n]
    float* As = smem + 128 * 128;   // [16 k][136 rows padded]

    int tid = threadIdx.x;
    int tx = tid & 15;              // col group
    int ty = tid >> 4;              // row group
    int row0 = blockIdx.x * 128;

    // stage full B (64 KB)
    #pragma unroll
    for (int it = 0; it < 16; ++it) {
        int idx = (it * 256 + tid) * 4;
        *(float4*)&Bs[idx] = *(const float4*)&B[idx];
    }

    float acc[8][8];
    #pragma unroll
    for (int i = 0; i < 8; i++)
        #pragma unroll
        for (int j = 0; j < 8; j++) acc[i][j] = 0.f;

    for (int k0 = 0; k0 < 128; k0 += 16) {
        __syncthreads();
        // load A tile transposed into As[k][row]
        #pragma unroll
        for (int p = 0; p < 2; p++) {
            int r = p * 64 + (tid >> 2);
            int c = (tid & 3) * 4;
            float4 v = make_float4(0.f, 0.f, 0.f, 0.f);
            int grow = row0 + r;
            if (grow < M) v = *(const float4*)&A[(size_t)grow * 128 + k0 + c];
            As[(c + 0) * 136 + r] = v.x;
            As[(c + 1) * 136 + r] = v.y;
            As[(c + 2) * 136 + r] = v.z;
            As[(c + 3) * 136 + r] = v.w;
        }
        __syncthreads();
        #pragma unroll
        for (int k = 0; k < 16; k++) {
            float4 a0 = *(float4*)&As[k * 136 + ty * 8];
            float4 a1 = *(float4*)&As[k * 136 + ty * 8 + 4];
            const float* brow = &Bs[(k0 + k) * 128];
            float4 b0 = *(float4*)&brow[tx * 4];
            float4 b1 = *(float4*)&brow[64 + tx * 4];
            float a[8] = {a0.x, a0.y, a0.z, a0.w, a1.x, a1.y, a1.z, a1.w};
            float b[8] = {b0.x, b0.y, b0.z, b0.w, b1.x, b1.y, b1.z, b1.w};
            #pragma unroll
            for (int i = 0; i < 8; i++)
                #pragma unroll
                for (int j = 0; j < 8; j++)
                    acc[i][j] = fmaf(a[i], b[j], acc[i][j]);
        }
    }

    float4 bias0 = *(const float4*)&bias[tx * 4];
    float4 bias1 = *(const float4*)&bias[64 + tx * 4];
    float bb[8] = {bias0.x, bias0.y, bias0.z, bias0.w, bias1.x, bias1.y, bias1.z, bias1.w};

    #pragma unroll
    for (int i = 0; i < 8; i++) {
        int grow = row0 + ty * 8 + i;
        if (grow >= M) continue;
        float o[8];
        #pragma unroll
        for (int j = 0; j < 8; j++) {
            float v = acc[i][j] + bb[j];
            if (MODE == 1) v = (v > 0.f) ? v : 0.01f * v;
            o[j] = v;
        }
        if (MODE == 2) {
            float4 r0 = *(const float4*)&R[(size_t)grow * 128 + tx * 4];
            float4 r1 = *(const float4*)&R[(size_t)grow * 128 + 64 + tx * 4];
            o[0] += r0.x; o[1] += r0.y; o[2] += r0.z; o[3] += r0.w;
            o[4] += r1.x; o[5] += r1.y; o[6] += r1.z; o[7] += r1.w;
        }
        *(float4*)&O[(size_t)grow * 128 + tx * 4]      = make_float4(o[0], o[1], o[2], o[3]);
        *(float4*)&O[(size_t)grow * 128 + 64 + tx * 4] = make_float4(o[4], o[5], o[6], o[7]);
    }
}

// ---------------- delta = tanh(h1 @ Wh2 + bh2), warp per node ----------------
__global__ void delta_kernel(const float* __restrict__ Wh2, const float* __restrict__ bh2, int N) {
    int warp = (blockIdx.x * blockDim.x + threadIdx.x) >> 5;
    int lane = threadIdx.x & 31;
    if (warp >= N) return;
    int k = lane * 4;
    float4 v = *(const float4*)&g_h1[(size_t)warp * 128 + k];
    float s0 = v.x * Wh2[k * 3 + 0] + v.y * Wh2[(k + 1) * 3 + 0] + v.z * Wh2[(k + 2) * 3 + 0] + v.w * Wh2[(k + 3) * 3 + 0];
    float s1 = v.x * Wh2[k * 3 + 1] + v.y * Wh2[(k + 1) * 3 + 1] + v.z * Wh2[(k + 2) * 3 + 1] + v.w * Wh2[(k + 3) * 3 + 1];
    float s2 = v.x * Wh2[k * 3 + 2] + v.y * Wh2[(k + 1) * 3 + 2] + v.z * Wh2[(k + 2) * 3 + 2] + v.w * Wh2[(k + 3) * 3 + 2];
    #pragma unroll
    for (int d = 16; d > 0; d >>= 1) {
        s0 += __shfl_xor_sync(0xffffffffu, s0, d);
        s1 += __shfl_xor_sync(0xffffffffu, s1, d);
        s2 += __shfl_xor_sync(0xffffffffu, s2, d);
    }
    if (lane == 0) {
        g_delta[warp * 3 + 0] = tanhf(s0 + bh2[0]);
        g_delta[warp * 3 + 1] = tanhf(s1 + bh2[1]);
        g_delta[warp * 3 + 2] = tanhf(s2 + bh2[2]);
    }
}

// ---------------- edge aggregation: warp per dst node, register max ----------------
__global__ void agg_kernel(const float* __restrict__ pos, const float* __restrict__ Wf, int N) {
    int warp = (blockIdx.x * blockDim.x + threadIdx.x) >> 5;
    int lane = threadIdx.x & 31;
    if (warp >= N) return;
    int c = lane * 4;
    float4 w0 = *(const float4*)&Wf[c];            // Wf row 0 (rel.x)
    float4 w1 = *(const float4*)&Wf[128 + c];      // Wf row 1 (rel.y)
    float4 w2 = *(const float4*)&Wf[256 + c];      // Wf row 2 (rel.z)
    float bx = g_delta[warp * 3 + 0] - pos[warp * 3 + 0];
    float by = g_delta[warp * 3 + 1] - pos[warp * 3 + 1];
    float bz = g_delta[warp * 3 + 2] - pos[warp * 3 + 2];
    int p0 = g_off[warp], p1 = g_off[warp + 1];
    float4 acc = make_float4(-INFINITY, -INFINITY, -INFINITY, -INFINITY);
    for (int p = p0; p < p1; ++p) {
        int s = g_esrc[p];
        float rx = pos[s * 3 + 0] + bx;
        float ry = pos[s * 3 + 1] + by;
        float rz = pos[s * 3 + 2] + bz;
        float4 v = *(const float4*)&g_xf[(size_t)s * 128 + c];
        float m0 = fmaf(rz, w2.x, fmaf(ry, w1.x, fmaf(rx, w0.x, v.x)));
        float m1 = fmaf(rz, w2.y, fmaf(ry, w1.y, fmaf(rx, w0.y, v.y)));
        float m2 = fmaf(rz, w2.z, fmaf(ry, w1.z, fmaf(rx, w0.z, v.z)));
        float m3 = fmaf(rz, w2.w, fmaf(ry, w1.w, fmaf(rx, w0.w, v.w)));
        acc.x = fmaxf(acc.x, m0);
        acc.y = fmaxf(acc.y, m1);
        acc.z = fmaxf(acc.z, m2);
        acc.w = fmaxf(acc.w, m3);
    }
    float4 o;
    if (p1 > p0) {
        // leaky_relu is monotone increasing: lrelu(max) == max(lrelu)
        o.x = (acc.x > 0.f) ? acc.x : 0.01f * acc.x;
        o.y = (acc.y > 0.f) ? acc.y : 0.01f * acc.y;
        o.z = (acc.z > 0.f) ? acc.z : 0.01f * acc.z;
        o.w = (acc.w > 0.f) ? acc.w : 0.01f * acc.w;
    } else {
        o = make_float4(0.f, 0.f, 0.f, 0.f);   // empty segment -> 0
    }
    *(float4*)&g_agg[(size_t)warp * 128 + c] = o;
}

// ---------------- launch ----------------
extern "C" void kernel_launch(void* const* d_in, const int* in_sizes, int n_in,
                              void* d_out, int out_size) {
    const float* x    = (const float*)d_in[0];
    const float* pos  = (const float*)d_in[1];
    const void*  ei   = d_in[2];
    const float* Wh1  = (const float*)d_in[3];
    const float* bh1  = (const float*)d_in[4];
    const float* Wh2  = (const float*)d_in[5];
    const float* bh2  = (const float*)d_in[6];
    const float* Wf   = (const float*)d_in[7];
    const float* bf   = (const float*)d_in[8];
    const float* Wg1  = (const float*)d_in[9];
    const float* bg1  = (const float*)d_in[10];
    const float* Wg2  = (const float*)d_in[11];
    const float* bg2  = (const float*)d_in[12];
    float* out = (float*)d_out;

    int M = in_sizes[0] / CDIM;     // 50000
    int E = in_sizes[2] / 2;        // 800000

    const int GEMM_SMEM = (128 * 128 + 16 * 136) * sizeof(float);  // 74,240 B
    cudaFuncSetAttribute(gemm128_kernel<0>, cudaFuncAttributeMaxDynamicSharedMemorySize, GEMM_SMEM);
    cudaFuncSetAttribute(gemm128_kernel<1>, cudaFuncAttributeMaxDynamicSharedMemorySize, GEMM_SMEM);
    cudaFuncSetAttribute(gemm128_kernel<2>, cudaFuncAttributeMaxDynamicSharedMemorySize, GEMM_SMEM);

    float *h1p, *xfp, *aggp, *tp;
    cudaGetSymbolAddress((void**)&h1p,  g_h1);
    cudaGetSymbolAddress((void**)&xfp,  g_xf);
    cudaGetSymbolAddress((void**)&aggp, g_agg);
    cudaGetSymbolAddress((void**)&tp,   g_t);

    int gemm_blocks = (M + 127) / 128;
    int eblocks = (E + 255) / 256;
    int nblocks = (M + 255) / 256;
    int wblocks = (M + 7) / 8;  // warp-per-node kernels, 8 warps/block

    // CSR build
    detect_kernel<<<1, 32>>>((const unsigned int*)ei, E);
    zero_cnt_kernel<<<nblocks, 256>>>(M);
    convert_hist_kernel<<<eblocks, 256>>>(ei, E);
    scan_kernel<<<1, 1024>>>(M);
    scatter_kernel<<<eblocks, 256>>>(E);

    // node-level GEMMs on x
    gemm128_kernel<1><<<gemm_blocks, 256, GEMM_SMEM>>>(x, Wh1, bh1, nullptr, h1p, M);       // h1 = lrelu(x@Wh1+bh1)
    gemm128_kernel<0><<<gemm_blocks, 256, GEMM_SMEM>>>(x, Wf + 3 * 128, bf, nullptr, xfp, M); // xf = x@Wf_x + bf
    delta_kernel<<<wblocks, 256>>>(Wh2, bh2, M);                                            // delta = tanh(h1@Wh2+bh2)

    // edge aggregation (segment max)
    agg_kernel<<<wblocks, 256>>>(pos, Wf, M);

    // output MLP + residual
    gemm128_kernel<1><<<gemm_blocks, 256, GEMM_SMEM>>>(aggp, Wg1, bg1, nullptr, tp, M);     // t = lrelu(agg@Wg1+bg1)
    gemm128_kernel<2><<<gemm_blocks, 256, GEMM_SMEM>>>(tp, Wg2, bg2, x, out, M);            // out = t@Wg2+bg2+x
}

// round 2
// speedup vs baseline: 1.2901x; 1.2901x over previous
#include <cuda_runtime.h>
#include <math.h>
#include <stdint.h>

#define NMAX 50000
#define EMAX 800000
#define CDIM 128
#define PADA 136   // transposed A-chunk row pad (floats)
#define PADT 132   // t-tile row pitch (floats), 16B-aligned rows

// ---------------- device scratch ----------------
__device__ int   g_is64;
__device__ float g_xf [(size_t)NMAX * CDIM];
__device__ float g_agg[(size_t)NMAX * CDIM];
__device__ float g_delta[(size_t)NMAX * 3];
__device__ int   g_src [EMAX];
__device__ int   g_dst [EMAX];
__device__ int   g_esrc[EMAX];
__device__ int   g_cnt [NMAX];
__device__ int   g_cur [NMAX];
__device__ int   g_off [NMAX + 1];
__device__ int   g_bsum[64];
__device__ int   g_bpre[64];

// ---------------- f32x2 helpers ----------------
__device__ __forceinline__ unsigned long long splat2(float a) {
    unsigned long long r;
    asm("mov.b64 %0, {%1, %1};" : "=l"(r) : "f"(a));
    return r;
}
__device__ __forceinline__ void fma2(unsigned long long& d, unsigned long long a, unsigned long long b) {
    asm("fma.rn.f32x2 %0, %1, %2, %0;" : "+l"(d) : "l"(a), "l"(b));
}
__device__ __forceinline__ float2 unpk(unsigned long long v) {
    float lo, hi;
    asm("mov.b64 {%0, %1}, %2;" : "=f"(lo), "=f"(hi) : "l"(v));
    return make_float2(lo, hi);
}
__device__ __forceinline__ float lrelu(float v) { return (v > 0.f) ? v : 0.01f * v; }

// ---------------- dtype detection (int64 vs int32 edge_index) ----------------
__global__ void detect_kernel(const unsigned int* __restrict__ w, int E) {
    int nz = 0;
    int lim = 2 * E;
    for (int i = threadIdx.x; i < 256; i += 32) {
        int wi = 2 * i + 1;
        if (wi < lim) nz |= (w[wi] != 0u);
    }
    nz = __any_sync(0xffffffffu, nz);
    if (threadIdx.x == 0) g_is64 = nz ? 0 : 1;
}

__global__ void zero_cnt_kernel(int n) {
    int i = blockIdx.x * blockDim.x + threadIdx.x;
    if (i < n) { g_cnt[i] = 0; g_cur[i] = 0; }
}

__global__ void convert_hist_kernel(const void* __restrict__ ei, int E) {
    int i = blockIdx.x * blockDim.x + threadIdx.x;
    if (i >= E) return;
    int s, d;
    if (g_is64) {
        const long long* p = (const long long*)ei;
        s = (int)p[i];
        d = (int)p[E + i];
    } else {
        const int* p = (const int*)ei;
        s = p[i];
        d = p[E + i];
    }
    g_src[i] = s;
    g_dst[i] = d;
    atomicAdd(&g_cnt[d], 1);
}

// ---------------- hierarchical scan: A (per-block), B (block sums), C (add) ----------------
__global__ void scanA_kernel(int n) {
    __shared__ int wsum[32];
    int tid = threadIdx.x, lane = tid & 31, wid = tid >> 5;
    int i = blockIdx.x * 1024 + tid;
    int v = (i < n) ? g_cnt[i] : 0;
    int x = v;
    #pragma unroll
    for (int d = 1; d < 32; d <<= 1) {
        int t = __shfl_up_sync(0xffffffffu, x, d);
        if (lane >= d) x += t;
    }
    if (lane == 31) wsum[wid] = x;
    __syncthreads();
    if (wid == 0) {
        int s = wsum[lane];
        #pragma unroll
        for (int d = 1; d < 32; d <<= 1) {
            int t = __shfl_up_sync(0xffffffffu, s, d);
            if (lane >= d) s += t;
        }
        wsum[lane] = s;
    }
    __syncthreads();
    if (wid > 0) x += wsum[wid - 1];
    if (i < n) g_off[i + 1] = x;
    if (tid == 1023) g_bsum[blockIdx.x] = x;
}

__global__ void scanB_kernel(int nb) {
    __shared__ int ws[2];
    int t = threadIdx.x, lane = t & 31, w = t >> 5;
    int v = (t < nb) ? g_bsum[t] : 0;
    int x = v;
    #pragma unroll
    for (int d = 1; d < 32; d <<= 1) {
        int u = __shfl_up_sync(0xffffffffu, x, d);
        if (lane >= d) x += u;
    }
    if (lane == 31) ws[w] = x;
    __syncthreads();
    if (w == 1) x += ws[0];
    if (t < nb) g_bpre[t] = x - v;   // exclusive prefix
}

__global__ void scanC_kernel(int n) {
    int i = blockIdx.x * 1024 + threadIdx.x;
    int add = g_bpre[blockIdx.x];
    if (i < n) g_off[i + 1] += add;
    if (i == 0) g_off[0] = 0;
}

__global__ void scatter_kernel(int E) {
    int i = blockIdx.x * blockDim.x + threadIdx.x;
    if (i >= E) return;
    int d = g_dst[i];
    int p = g_off[d] + atomicAdd(&g_cur[d], 1);
    g_esrc[p] = g_src[i];
}

// ---------------- shared GEMM core: acc[8][4] (f32x2 pairs along columns) ----------------
__device__ __forceinline__ void gemm_core(
    const float* __restrict__ A, int M, int row0,
    const float* Bs, float* As, unsigned long long acc[8][4],
    int tid, int tx, int ty)
{
    for (int k0 = 0; k0 < 128; k0 += 16) {
        __syncthreads();
        #pragma unroll
        for (int p = 0; p < 2; p++) {
            int r = p * 64 + (tid >> 2);
            int c = (tid & 3) * 4;
            float4 v = make_float4(0.f, 0.f, 0.f, 0.f);
            int g = row0 + r;
            if (g < M) v = *(const float4*)&A[(size_t)g * 128 + k0 + c];
            As[(c + 0) * PADA + r] = v.x;
            As[(c + 1) * PADA + r] = v.y;
            As[(c + 2) * PADA + r] = v.z;
            As[(c + 3) * PADA + r] = v.w;
        }
        __syncthreads();
        #pragma unroll
        for (int k = 0; k < 16; k++) {
            float4 a0 = *(float4*)&As[k * PADA + ty * 8];
            float4 a1 = *(float4*)&As[k * PADA + ty * 8 + 4];
            const float* br = &Bs[(k0 + k) * 128];
            ulonglong2 b01 = *(const ulonglong2*)&br[tx * 4];
            ulonglong2 b23 = *(const ulonglong2*)&br[64 + tx * 4];
            float av[8] = {a0.x, a0.y, a0.z, a0.w, a1.x, a1.y, a1.z, a1.w};
            #pragma unroll
            for (int i = 0; i < 8; i++) {
                unsigned long long as_ = splat2(av[i]);
                fma2(acc[i][0], as_, b01.x);
                fma2(acc[i][1], as_, b01.y);
                fma2(acc[i][2], as_, b23.x);
                fma2(acc[i][3], as_, b23.y);
            }
        }
    }
}

// ---------------- xf = x @ Wf_x + bf ----------------
__global__ __launch_bounds__(256, 2)
void gemm_bias_kernel(const float* __restrict__ A, const float* __restrict__ B,
                      const float* __restrict__ bias, float* __restrict__ O, int M) {
    extern __shared__ float sm[];
    float* Bs = sm;                // 128*128
    float* As = sm + 16384;        // 16*PADA
    int tid = threadIdx.x, tx = tid & 15, ty = tid >> 4;
    int row0 = blockIdx.x * 128;

    #pragma unroll
    for (int it = 0; it < 16; ++it) {
        int idx = (it * 256 + tid) * 4;
        *(float4*)&Bs[idx] = *(const float4*)&B[idx];
    }
    unsigned long long acc[8][4];
    #pragma unroll
    for (int i = 0; i < 8; i++)
        #pragma unroll
        for (int j = 0; j < 4; j++) acc[i][j] = 0ull;

    gemm_core(A, M, row0, Bs, As, acc, tid, tx, ty);

    float4 bA = *(const float4*)&bias[tx * 4];
    float4 bB = *(const float4*)&bias[64 + tx * 4];
    #pragma unroll
    for (int i = 0; i < 8; i++) {
        int grow = row0 + ty * 8 + i;
        if (grow >= M) continue;
        float2 f0 = unpk(acc[i][0]), f1 = unpk(acc[i][1]);
        float2 f2 = unpk(acc[i][2]), f3 = unpk(acc[i][3]);
        float4 o0 = make_float4(f0.x + bA.x, f0.y + bA.y, f1.x + bA.z, f1.y + bA.w);
        float4 o1 = make_float4(f2.x + bB.x, f2.y + bB.y, f3.x + bB.z, f3.y + bB.w);
        *(float4*)&O[(size_t)grow * 128 + tx * 4]      = o0;
        *(float4*)&O[(size_t)grow * 128 + 64 + tx * 4] = o1;
    }
}

// ---------------- delta = tanh(lrelu(x@Wh1+bh1) @ Wh2 + bh2), fused ----------------
__global__ __launch_bounds__(256, 2)
void gemm_hdelta_kernel(const float* __restrict__ A, const float* __restrict__ B,
                        const float* __restrict__ bias,
                        const float* __restrict__ Wh2, const float* __restrict__ bh2, int M) {
    extern __shared__ float sm[];
    float* Bs   = sm;                    // 16384
    float* As   = sm + 16384;            // 16*PADA = 2176
    float* sW2  = sm + 16384 + 2176;     // 384
    float* sdel = sm + 16384 + 2176 + 384; // 128*3
    int tid = threadIdx.x, tx = tid & 15, ty = tid >> 4;
    int row0 = blockIdx.x * 128;

    #pragma unroll
    for (int it = 0; it < 16; ++it) {
        int idx = (it * 256 + tid) * 4;
        *(float4*)&Bs[idx] = *(const float4*)&B[idx];
    }
    if (tid < 96) *(float4*)&sW2[tid * 4] = *(const float4*)&Wh2[tid * 4];

    unsigned long long acc[8][4];
    #pragma unroll
    for (int i = 0; i < 8; i++)
        #pragma unroll
        for (int j = 0; j < 4; j++) acc[i][j] = 0ull;

    gemm_core(A, M, row0, Bs, As, acc, tid, tx, ty);

    float4 bA = *(const float4*)&bias[tx * 4];
    float4 bB = *(const float4*)&bias[64 + tx * 4];
    float bb[8] = {bA.x, bA.y, bA.z, bA.w, bB.x, bB.y, bB.z, bB.w};

    #pragma unroll
    for (int i = 0; i < 8; i++) {
        float p0 = 0.f, p1 = 0.f, p2 = 0.f;
        #pragma unroll
        for (int j = 0; j < 4; j++) {
            int c0 = (j < 2) ? (tx * 4 + j * 2) : (64 + tx * 4 + (j - 2) * 2);
            float2 f = unpk(acc[i][j]);
            f.x = lrelu(f.x + bb[j * 2 + 0]);
            f.y = lrelu(f.y + bb[j * 2 + 1]);
            p0 += f.x * sW2[c0 * 3 + 0] + f.y * sW2[(c0 + 1) * 3 + 0];
            p1 += f.x * sW2[c0 * 3 + 1] + f.y * sW2[(c0 + 1) * 3 + 1];
            p2 += f.x * sW2[c0 * 3 + 2] + f.y * sW2[(c0 + 1) * 3 + 2];
        }
        #pragma unroll
        for (int d = 1; d < 16; d <<= 1) {
            p0 += __shfl_xor_sync(0xffffffffu, p0, d);
            p1 += __shfl_xor_sync(0xffffffffu, p1, d);
            p2 += __shfl_xor_sync(0xffffffffu, p2, d);
        }
        if (tx == 0) {
            int r = ty * 8 + i;
            sdel[r * 3 + 0] = p0;
            sdel[r * 3 + 1] = p1;
            sdel[r * 3 + 2] = p2;
        }
    }
    __syncthreads();
    if (tid < 128) {
        int grow = row0 + tid;
        if (grow < M) {
            g_delta[grow * 3 + 0] = tanhf(sdel[tid * 3 + 0] + bh2[0]);
            g_delta[grow * 3 + 1] = tanhf(sdel[tid * 3 + 1] + bh2[1]);
            g_delta[grow * 3 + 2] = tanhf(sdel[tid * 3 + 2] + bh2[2]);
        }
    }
}

// ---------------- edge aggregation: warp per dst node, register max ----------------
__global__ void agg_kernel(const float* __restrict__ pos, const float* __restrict__ Wf, int N) {
    int warp = (blockIdx.x * blockDim.x + threadIdx.x) >> 5;
    int lane = threadIdx.x & 31;
    if (warp >= N) return;
    int c = lane * 4;
    float4 w0 = *(const float4*)&Wf[c];
    float4 w1 = *(const float4*)&Wf[128 + c];
    float4 w2 = *(const float4*)&Wf[256 + c];
    float bx = g_delta[warp * 3 + 0] - pos[warp * 3 + 0];
    float by = g_delta[warp * 3 + 1] - pos[warp * 3 + 1];
    float bz = g_delta[warp * 3 + 2] - pos[warp * 3 + 2];
    int p0 = g_off[warp], p1 = g_off[warp + 1];
    float4 acc = make_float4(-INFINITY, -INFINITY, -INFINITY, -INFINITY);
    for (int p = p0; p < p1; ++p) {
        int s = g_esrc[p];
        float rx = pos[s * 3 + 0] + bx;
        float ry = pos[s * 3 + 1] + by;
        float rz = pos[s * 3 + 2] + bz;
        float4 v = *(const float4*)&g_xf[(size_t)s * 128 + c];
        float m0 = fmaf(rz, w2.x, fmaf(ry, w1.x, fmaf(rx, w0.x, v.x)));
        float m1 = fmaf(rz, w2.y, fmaf(ry, w1.y, fmaf(rx, w0.y, v.y)));
        float m2 = fmaf(rz, w2.z, fmaf(ry, w1.z, fmaf(rx, w0.z, v.z)));
        float m3 = fmaf(rz, w2.w, fmaf(ry, w1.w, fmaf(rx, w0.w, v.w)));
        acc.x = fmaxf(acc.x, m0);
        acc.y = fmaxf(acc.y, m1);
        acc.z = fmaxf(acc.z, m2);
        acc.w = fmaxf(acc.w, m3);
    }
    float4 o;
    if (p1 > p0) {
        o.x = lrelu(acc.x); o.y = lrelu(acc.y);
        o.z = lrelu(acc.z); o.w = lrelu(acc.w);
    } else {
        o = make_float4(0.f, 0.f, 0.f, 0.f);
    }
    *(float4*)&g_agg[(size_t)warp * 128 + c] = o;
}

// ---------------- fused: out = lrelu(agg@Wg1+bg1)@Wg2 + bg2 + x ----------------
__global__ __launch_bounds__(256, 1)
void gemm_out_kernel(const float* __restrict__ A, const float* __restrict__ B1,
                     const float* __restrict__ b1, const float* __restrict__ B2,
                     const float* __restrict__ b2, const float* __restrict__ X,
                     float* __restrict__ O, int M) {
    extern __shared__ float sm[];
    float* Bs1 = sm;                       // 16384
    float* Bs2 = sm + 16384;               // 16384
    float* Ts  = sm + 32768;               // 128*PADT = 16896
    float* As  = sm + 32768 + 16896;       // 16*PADA = 2176
    int tid = threadIdx.x, tx = tid & 15, ty = tid >> 4;
    int row0 = blockIdx.x * 128;

    #pragma unroll
    for (int it = 0; it < 16; ++it) {
        int idx = (it * 256 + tid) * 4;
        *(float4*)&Bs1[idx] = *(const float4*)&B1[idx];
        *(float4*)&Bs2[idx] = *(const float4*)&B2[idx];
    }
    unsigned long long acc[8][4];
    #pragma unroll
    for (int i = 0; i < 8; i++)
        #pragma unroll
        for (int j = 0; j < 4; j++) acc[i][j] = 0ull;

    gemm_core(A, M, row0, Bs1, As, acc, tid, tx, ty);

    // stage1 epilogue: bias + lrelu -> Ts (row-major [128][PADT])
    {
        float4 bA = *(const float4*)&b1[tx * 4];
        float4 bB = *(const float4*)&b1[64 + tx * 4];
        #pragma unroll
        for (int i = 0; i < 8; i++) {
            int r = ty * 8 + i;
            float2 f0 = unpk(acc[i][0]), f1 = unpk(acc[i][1]);
            float2 f2 = unpk(acc[i][2]), f3 = unpk(acc[i][3]);
            float4 v0 = make_float4(lrelu(f0.x + bA.x), lrelu(f0.y + bA.y),
                                    lrelu(f1.x + bA.z), lrelu(f1.y + bA.w));
            float4 v1 = make_float4(lrelu(f2.x + bB.x), lrelu(f2.y + bB.y),
                                    lrelu(f3.x + bB.z), lrelu(f3.y + bB.w));
            *(float4*)&Ts[r * PADT + tx * 4]      = v0;
            *(float4*)&Ts[r * PADT + 64 + tx * 4] = v1;
        }
    }
    __syncthreads();

    // stage2: out = Ts @ Wg2
    #pragma unroll
    for (int i = 0; i < 8; i++)
        #pragma unroll
        for (int j = 0; j < 4; j++) acc[i][j] = 0ull;

    #pragma unroll 4
    for (int k = 0; k < 128; k++) {
        const float* br = &Bs2[k * 128];
        ulonglong2 b01 = *(const ulonglong2*)&br[tx * 4];
        ulonglong2 b23 = *(const ulonglong2*)&br[64 + tx * 4];
        #pragma unroll
        for (int i = 0; i < 8; i++) {
            unsigned long long as_ = splat2(Ts[(ty * 8 + i) * PADT + k]);
            fma2(acc[i][0], as_, b01.x);
            fma2(acc[i][1], as_, b01.y);
            fma2(acc[i][2], as_, b23.x);
            fma2(acc[i][3], as_, b23.y);
        }
    }

    float4 bA = *(const float4*)&b2[tx * 4];
    float4 bB = *(const float4*)&b2[64 + tx * 4];
    #pragma unroll
    for (int i = 0; i < 8; i++) {
        int grow = row0 + ty * 8 + i;
        if (grow >= M) continue;
        float2 f0 = unpk(acc[i][0]), f1 = unpk(acc[i][1]);
        float2 f2 = unpk(acc[i][2]), f3 = unpk(acc[i][3]);
        float4 r0 = *(const float4*)&X[(size_t)grow * 128 + tx * 4];
        float4 r1 = *(const float4*)&X[(size_t)grow * 128 + 64 + tx * 4];
        float4 o0 = make_float4(f0.x + bA.x + r0.x, f0.y + bA.y + r0.y,
                                f1.x + bA.z + r0.z, f1.y + bA.w + r0.w);
        float4 o1 = make_float4(f2.x + bB.x + r1.x, f2.y + bB.y + r1.y,
                                f3.x + bB.z + r1.z, f3.y + bB.w + r1.w);
        *(float4*)&O[(size_t)grow * 128 + tx * 4]      = o0;
        *(float4*)&O[(size_t)grow * 128 + 64 + tx * 4] = o1;
    }
}

// ---------------- launch ----------------
extern "C" void kernel_launch(void* const* d_in, const int* in_sizes, int n_in,
                              void* d_out, int out_size) {
    const float* x   = (const float*)d_in[0];
    const float* pos = (const float*)d_in[1];
    const void*  ei  = d_in[2];
    const float* Wh1 = (const float*)d_in[3];
    const float* bh1 = (const float*)d_in[4];
    const float* Wh2 = (const float*)d_in[5];
    const float* bh2 = (const float*)d_in[6];
    const float* Wf  = (const float*)d_in[7];
    const float* bf  = (const float*)d_in[8];
    const float* Wg1 = (const float*)d_in[9];
    const float* bg1 = (const float*)d_in[10];
    const float* Wg2 = (const float*)d_in[11];
    const float* bg2 = (const float*)d_in[12];
    float* out = (float*)d_out;

    int M = in_sizes[0] / CDIM;   // 50000
    int E = in_sizes[2] / 2;      // 800000

    const int SM_BIAS   = (16384 + 16 * PADA) * sizeof(float);
    const int SM_HDELTA = (16384 + 16 * PADA + 384 + 128 * 3) * sizeof(float);
    const int SM_OUT    = (16384 * 2 + 128 * PADT + 16 * PADA) * sizeof(float);
    cudaFuncSetAttribute(gemm_bias_kernel,   cudaFuncAttributeMaxDynamicSharedMemorySize, SM_BIAS);
    cudaFuncSetAttribute(gemm_hdelta_kernel, cudaFuncAttributeMaxDynamicSharedMemorySize, SM_HDELTA);
    cudaFuncSetAttribute(gemm_out_kernel,    cudaFuncAttributeMaxDynamicSharedMemorySize, SM_OUT);

    float *xfp, *aggp;
    cudaGetSymbolAddress((void**)&xfp,  g_xf);
    cudaGetSymbolAddress((void**)&aggp, g_agg);

    int gemm_blocks = (M + 127) / 128;
    int eblocks = (E + 255) / 256;
    int nblocks = (M + 255) / 256;
    int sblocks = (M + 1023) / 1024;
    int wblocks = (M + 7) / 8;

    // lazy-created side-stream resources (same work every call; handles reused)
    static cudaStream_t s_side = nullptr;
    static cudaEvent_t  s_e0 = nullptr, s_e1 = nullptr;
    if (s_side == nullptr) {
        cudaStreamCreateWithFlags(&s_side, cudaStreamNonBlocking);
        cudaEventCreateWithFlags(&s_e0, cudaEventDisableTiming);
        cudaEventCreateWithFlags(&s_e1, cudaEventDisableTiming);
    }

    // fork: CSR build on side stream
    cudaEventRecord(s_e0, 0);
    cudaStreamWaitEvent(s_side, s_e0, 0);
    detect_kernel<<<1, 32, 0, s_side>>>((const unsigned int*)ei, E);
    zero_cnt_kernel<<<nblocks, 256, 0, s_side>>>(M);
    convert_hist_kernel<<<eblocks, 256, 0, s_side>>>(ei, E);
    scanA_kernel<<<sblocks, 1024, 0, s_side>>>(M);
    scanB_kernel<<<1, 64, 0, s_side>>>(sblocks);
    scanC_kernel<<<sblocks, 1024, 0, s_side>>>(M);
    scatter_kernel<<<eblocks, 256, 0, s_side>>>(E);
    cudaEventRecord(s_e1, s_side);

    // main stream: node GEMMs (independent of CSR)
    gemm_hdelta_kernel<<<gemm_blocks, 256, SM_HDELTA>>>(x, Wh1, bh1, Wh2, bh2, M);
    gemm_bias_kernel<<<gemm_blocks, 256, SM_BIAS>>>(x, Wf + 3 * 128, bf, xfp, M);

    // join, then aggregate + output MLP
    cudaStreamWaitEvent(0, s_e1, 0);
    agg_kernel<<<wblocks, 256>>>(pos, Wf, M);
    gemm_out_kernel<<<gemm_blocks, 256, SM_OUT>>>(aggp, Wg1, bg1, Wg2, bg2, x, out, M);
}

// round 4
// speedup vs baseline: 1.3500x; 1.0464x over previous
#include <cuda_runtime.h>
#include <math.h>
#include <stdint.h>

#define NMAX 50000
#define EMAX 800000
#define CDIM 128
#define PADA 136   // transposed A-chunk row pad (floats)
#define PADT 132   // t-tile row pitch (floats), 16B-aligned rows

// ---------------- device scratch ----------------
__device__ int   g_is64;
__device__ float g_xf [(size_t)NMAX * CDIM];
__device__ float g_agg[(size_t)NMAX * CDIM];
__device__ float g_delta[(size_t)NMAX * 3];
__device__ int   g_src [EMAX];
__device__ int   g_dst [EMAX];
__device__ int   g_esrc[EMAX];
__device__ int   g_cnt [NMAX];
__device__ int   g_cur [NMAX];
__device__ int   g_off [NMAX + 1];
__device__ int   g_bsum[64];
__device__ int   g_bpre[64];

// ---------------- f32x2 helpers ----------------
__device__ __forceinline__ unsigned long long splat2(float a) {
    unsigned long long r;
    asm("mov.b64 %0, {%1, %1};" : "=l"(r) : "f"(a));
    return r;
}
__device__ __forceinline__ void fma2(unsigned long long& d, unsigned long long a, unsigned long long b) {
    asm("fma.rn.f32x2 %0, %1, %2, %0;" : "+l"(d) : "l"(a), "l"(b));
}
__device__ __forceinline__ float2 unpk(unsigned long long v) {
    float lo, hi;
    asm("mov.b64 {%0, %1}, %2;" : "=f"(lo), "=f"(hi) : "l"(v));
    return make_float2(lo, hi);
}
__device__ __forceinline__ float lrelu(float v) { return (v > 0.f) ? v : 0.01f * v; }

// ---------------- dtype detection (int64 vs int32 edge_index) ----------------
__global__ void detect_kernel(const unsigned int* __restrict__ w, int E) {
    int nz = 0;
    int lim = 2 * E;
    for (int i = threadIdx.x; i < 256; i += 32) {
        int wi = 2 * i + 1;
        if (wi < lim) nz |= (w[wi] != 0u);
    }
    nz = __any_sync(0xffffffffu, nz);
    if (threadIdx.x == 0) g_is64 = nz ? 0 : 1;
}

__global__ void zero_cnt_kernel(int n) {
    int i = blockIdx.x * blockDim.x + threadIdx.x;
    if (i < n) { g_cnt[i] = 0; g_cur[i] = 0; }
}

__global__ void convert_hist_kernel(const void* __restrict__ ei, int E) {
    int i = blockIdx.x * blockDim.x + threadIdx.x;
    if (i >= E) return;
    int s, d;
    if (g_is64) {
        const long long* p = (const long long*)ei;
        s = (int)p[i];
        d = (int)p[E + i];
    } else {
        const int* p = (const int*)ei;
        s = p[i];
        d = p[E + i];
    }
    g_src[i] = s;
    g_dst[i] = d;
    atomicAdd(&g_cnt[d], 1);
}

// ---------------- hierarchical scan ----------------
__global__ void scanA_kernel(int n) {
    __shared__ int wsum[32];
    int tid = threadIdx.x, lane = tid & 31, wid = tid >> 5;
    int i = blockIdx.x * 1024 + tid;
    int v = (i < n) ? g_cnt[i] : 0;
    int x = v;
    #pragma unroll
    for (int d = 1; d < 32; d <<= 1) {
        int t = __shfl_up_sync(0xffffffffu, x, d);
        if (lane >= d) x += t;
    }
    if (lane == 31) wsum[wid] = x;
    __syncthreads();
    if (wid == 0) {
        int s = wsum[lane];
        #pragma unroll
        for (int d = 1; d < 32; d <<= 1) {
            int t = __shfl_up_sync(0xffffffffu, s, d);
            if (lane >= d) s += t;
        }
        wsum[lane] = s;
    }
    __syncthreads();
    if (wid > 0) x += wsum[wid - 1];
    if (i < n) g_off[i + 1] = x;
    if (tid == 1023) g_bsum[blockIdx.x] = x;
}

__global__ void scanB_kernel(int nb) {
    __shared__ int ws[2];
    int t = threadIdx.x, lane = t & 31, w = t >> 5;
    int v = (t < nb) ? g_bsum[t] : 0;
    int x = v;
    #pragma unroll
    for (int d = 1; d < 32; d <<= 1) {
        int u = __shfl_up_sync(0xffffffffu, x, d);
        if (lane >= d) x += u;
    }
    if (lane == 31) ws[w] = x;
    __syncthreads();
    if (w == 1) x += ws[0];
    if (t < nb) g_bpre[t] = x - v;
}

__global__ void scanC_kernel(int n) {
    int i = blockIdx.x * 1024 + threadIdx.x;
    int add = g_bpre[blockIdx.x];
    if (i < n) g_off[i + 1] += add;
    if (i == 0) g_off[0] = 0;
}

__global__ void scatter_kernel(int E) {
    int i = blockIdx.x * blockDim.x + threadIdx.x;
    if (i >= E) return;
    int d = g_dst[i];
    int p = g_off[d] + atomicAdd(&g_cur[d], 1);
    g_esrc[p] = g_src[i];
}

// ---------------- GEMM core with register-prefetch pipeline ----------------
// acc[8][4]: 8 rows x 4 f32x2 column-pairs. A-chunk staging: chunk c+1's LDGs
// are issued right after chunk c's STS, so gmem latency overlaps compute(c).
__device__ __forceinline__ void gemm_core(
    const float* __restrict__ A, int M, int row0,
    const float* Bs, float* As, unsigned long long acc[8][4],
    int tid, int tx, int ty)
{
    int r_ = tid >> 2;               // 0..63
    int c_ = (tid & 3) * 4;          // 0,4,8,12
    int g0 = row0 + r_;
    int g1 = row0 + 64 + r_;
    const float* A0 = &A[(size_t)g0 * 128 + c_];
    const float* A1 = &A[(size_t)g1 * 128 + c_];
    bool ok0 = g0 < M, ok1 = g1 < M;

    float4 v0 = make_float4(0.f, 0.f, 0.f, 0.f);
    float4 v1 = make_float4(0.f, 0.f, 0.f, 0.f);
    if (ok0) v0 = *(const float4*)A0;
    if (ok1) v1 = *(const float4*)A1;

    #pragma unroll
    for (int k0 = 0; k0 < 128; k0 += 16) {
        // store current chunk (transposed)
        As[(c_ + 0) * PADA + r_] = v0.x;
        As[(c_ + 1) * PADA + r_] = v0.y;
        As[(c_ + 2) * PADA + r_] = v0.z;
        As[(c_ + 3) * PADA + r_] = v0.w;
        As[(c_ + 0) * PADA + 64 + r_] = v1.x;
        As[(c_ + 1) * PADA + 64 + r_] = v1.y;
        As[(c_ + 2) * PADA + 64 + r_] = v1.z;
        As[(c_ + 3) * PADA + 64 + r_] = v1.w;
        // prefetch next chunk (latency hidden under compute below)
        if (k0 < 112) {
            v0 = make_float4(0.f, 0.f, 0.f, 0.f);
            v1 = make_float4(0.f, 0.f, 0.f, 0.f);
            if (ok0) v0 = *(const float4*)(A0 + k0 + 16);
            if (ok1) v1 = *(const float4*)(A1 + k0 + 16);
        }
        __syncthreads();
        #pragma unroll
        for (int k = 0; k < 16; k++) {
            float4 a0 = *(float4*)&As[k * PADA + ty * 8];
            float4 a1 = *(float4*)&As[k * PADA + ty * 8 + 4];
            const float* br = &Bs[(k0 + k) * 128];
            ulonglong2 b01 = *(const ulonglong2*)&br[tx * 4];
            ulonglong2 b23 = *(const ulonglong2*)&br[64 + tx * 4];
            float av[8] = {a0.x, a0.y, a0.z, a0.w, a1.x, a1.y, a1.z, a1.w};
            #pragma unroll
            for (int i = 0; i < 8; i++) {
                unsigned long long as_ = splat2(av[i]);
                fma2(acc[i][0], as_, b01.x);
                fma2(acc[i][1], as_, b01.y);
                fma2(acc[i][2], as_, b23.x);
                fma2(acc[i][3], as_, b23.y);
            }
        }
        __syncthreads();
    }
}

// ---------------- xf = x @ Wf_x + bf ----------------
__global__ __launch_bounds__(256, 2)
void gemm_bias_kernel(const float* __restrict__ A, const float* __restrict__ B,
                      const float* __restrict__ bias, float* __restrict__ O, int M) {
    extern __shared__ float sm[];
    float* Bs = sm;                // 128*128
    float* As = sm + 16384;        // 16*PADA
    int tid = threadIdx.x, tx = tid & 15, ty = tid >> 4;
    int row0 = blockIdx.x * 128;

    #pragma unroll
    for (int it = 0; it < 16; ++it) {
        int idx = (it * 256 + tid) * 4;
        *(float4*)&Bs[idx] = *(const float4*)&B[idx];
    }
    unsigned long long acc[8][4];
    #pragma unroll
    for (int i = 0; i < 8; i++)
        #pragma unroll
        for (int j = 0; j < 4; j++) acc[i][j] = 0ull;

    gemm_core(A, M, row0, Bs, As, acc, tid, tx, ty);

    float4 bA = *(const float4*)&bias[tx * 4];
    float4 bB = *(const float4*)&bias[64 + tx * 4];
    #pragma unroll
    for (int i = 0; i < 8; i++) {
        int grow = row0 + ty * 8 + i;
        if (grow >= M) continue;
        float2 f0 = unpk(acc[i][0]), f1 = unpk(acc[i][1]);
        float2 f2 = unpk(acc[i][2]), f3 = unpk(acc[i][3]);
        float4 o0 = make_float4(f0.x + bA.x, f0.y + bA.y, f1.x + bA.z, f1.y + bA.w);
        float4 o1 = make_float4(f2.x + bB.x, f2.y + bB.y, f3.x + bB.z, f3.y + bB.w);
        *(float4*)&O[(size_t)grow * 128 + tx * 4]      = o0;
        *(float4*)&O[(size_t)grow * 128 + 64 + tx * 4] = o1;
    }
}

// ---------------- delta = tanh(lrelu(x@Wh1+bh1) @ Wh2 + bh2), fused ----------------
__global__ __launch_bounds__(256, 2)
void gemm_hdelta_kernel(const float* __restrict__ A, const float* __restrict__ B,
                        const float* __restrict__ bias,
                        const float* __restrict__ Wh2, const float* __restrict__ bh2, int M) {
    extern __shared__ float sm[];
    float* Bs   = sm;                      // 16384
    float* As   = sm + 16384;              // 16*PADA = 2176
    float* sW2  = sm + 16384 + 2176;       // 384
    float* sdel = sm + 16384 + 2176 + 384; // 128*3
    int tid = threadIdx.x, tx = tid & 15, ty = tid >> 4;
    int row0 = blockIdx.x * 128;

    #pragma unroll
    for (int it = 0; it < 16; ++it) {
        int idx = (it * 256 + tid) * 4;
        *(float4*)&Bs[idx] = *(const float4*)&B[idx];
    }
    if (tid < 96) *(float4*)&sW2[tid * 4] = *(const float4*)&Wh2[tid * 4];

    unsigned long long acc[8][4];
    #pragma unroll
    for (int i = 0; i < 8; i++)
        #pragma unroll
        for (int j = 0; j < 4; j++) acc[i][j] = 0ull;

    gemm_core(A, M, row0, Bs, As, acc, tid, tx, ty);

    float4 bA = *(const float4*)&bias[tx * 4];
    float4 bB = *(const float4*)&bias[64 + tx * 4];
    float bb[8] = {bA.x, bA.y, bA.z, bA.w, bB.x, bB.y, bB.z, bB.w};

    #pragma unroll
    for (int i = 0; i < 8; i++) {
        float p0 = 0.f, p1 = 0.f, p2 = 0.f;
        #pragma unroll
        for (int j = 0; j < 4; j++) {
            int c0 = (j < 2) ? (tx * 4 + j * 2) : (64 + tx * 4 + (j - 2) * 2);
            float2 f = unpk(acc[i][j]);
            f.x = lrelu(f.x + bb[j * 2 + 0]);
            f.y = lrelu(f.y + bb[j * 2 + 1]);
            p0 += f.x * sW2[c0 * 3 + 0] + f.y * sW2[(c0 + 1) * 3 + 0];
            p1 += f.x * sW2[c0 * 3 + 1] + f.y * sW2[(c0 + 1) * 3 + 1];
            p2 += f.x * sW2[c0 * 3 + 2] + f.y * sW2[(c0 + 1) * 3 + 2];
        }
        #pragma unroll
        for (int d = 1; d < 16; d <<= 1) {
            p0 += __shfl_xor_sync(0xffffffffu, p0, d);
            p1 += __shfl_xor_sync(0xffffffffu, p1, d);
            p2 += __shfl_xor_sync(0xffffffffu, p2, d);
        }
        if (tx == 0) {
            int r = ty * 8 + i;
            sdel[r * 3 + 0] = p0;
            sdel[r * 3 + 1] = p1;
            sdel[r * 3 + 2] = p2;
        }
    }
    __syncthreads();
    if (tid < 128) {
        int grow = row0 + tid;
        if (grow < M) {
            g_delta[grow * 3 + 0] = tanhf(sdel[tid * 3 + 0] + bh2[0]);
            g_delta[grow * 3 + 1] = tanhf(sdel[tid * 3 + 1] + bh2[1]);
            g_delta[grow * 3 + 2] = tanhf(sdel[tid * 3 + 2] + bh2[2]);
        }
    }
}

// ---------------- edge aggregation: warp per dst node, unroll 2 ----------------
__global__ void agg_kernel(const float* __restrict__ pos, const float* __restrict__ Wf, int N) {
    int warp = (blockIdx.x * blockDim.x + threadIdx.x) >> 5;
    int lane = threadIdx.x & 31;
    if (warp >= N) return;
    int c = lane * 4;
    float4 w0 = *(const float4*)&Wf[c];
    float4 w1 = *(const float4*)&Wf[128 + c];
    float4 w2 = *(const float4*)&Wf[256 + c];
    float bx = g_delta[warp * 3 + 0] - pos[warp * 3 + 0];
    float by = g_delta[warp * 3 + 1] - pos[warp * 3 + 1];
    float bz = g_delta[warp * 3 + 2] - pos[warp * 3 + 2];
    int p0 = g_off[warp], p1 = g_off[warp + 1];
    float4 acc = make_float4(-INFINITY, -INFINITY, -INFINITY, -INFINITY);
    int p = p0;
    for (; p + 2 <= p1; p += 2) {
        int s0 = g_esrc[p], s1 = g_esrc[p + 1];
        float rx0 = pos[s0 * 3 + 0] + bx, ry0 = pos[s0 * 3 + 1] + by, rz0 = pos[s0 * 3 + 2] + bz;
        float rx1 = pos[s1 * 3 + 0] + bx, ry1 = pos[s1 * 3 + 1] + by, rz1 = pos[s1 * 3 + 2] + bz;
        float4 v0 = *(const float4*)&g_xf[(size_t)s0 * 128 + c];
        float4 v1 = *(const float4*)&g_xf[(size_t)s1 * 128 + c];
        acc.x = fmaxf(acc.x, fmaf(rz0, w2.x, fmaf(ry0, w1.x, fmaf(rx0, w0.x, v0.x))));
        acc.y = fmaxf(acc.y, fmaf(rz0, w2.y, fmaf(ry0, w1.y, fmaf(rx0, w0.y, v0.y))));
        acc.z = fmaxf(acc.z, fmaf(rz0, w2.z, fmaf(ry0, w1.z, fmaf(rx0, w0.z, v0.z))));
        acc.w = fmaxf(acc.w, fmaf(rz0, w2.w, fmaf(ry0, w1.w, fmaf(rx0, w0.w, v0.w))));
        acc.x = fmaxf(acc.x, fmaf(rz1, w2.x, fmaf(ry1, w1.x, fmaf(rx1, w0.x, v1.x))));
        acc.y = fmaxf(acc.y, fmaf(rz1, w2.y, fmaf(ry1, w1.y, fmaf(rx1, w0.y, v1.y))));
        acc.z = fmaxf(acc.z, fmaf(rz1, w2.z, fmaf(ry1, w1.z, fmaf(rx1, w0.z, v1.z))));
        acc.w = fmaxf(acc.w, fmaf(rz1, w2.w, fmaf(ry1, w1.w, fmaf(rx1, w0.w, v1.w))));
    }
    if (p < p1) {
        int s = g_esrc[p];
        float rx = pos[s * 3 + 0] + bx, ry = pos[s * 3 + 1] + by, rz = pos[s * 3 + 2] + bz;
        float4 v = *(const float4*)&g_xf[(size_t)s * 128 + c];
        acc.x = fmaxf(acc.x, fmaf(rz, w2.x, fmaf(ry, w1.x, fmaf(rx, w0.x, v.x))));
        acc.y = fmaxf(acc.y, fmaf(rz, w2.y, fmaf(ry, w1.y, fmaf(rx, w0.y, v.y))));
        acc.z = fmaxf(acc.z, fmaf(rz, w2.z, fmaf(ry, w1.z, fmaf(rx, w0.z, v.z))));
        acc.w = fmaxf(acc.w, fmaf(rz, w2.w, fmaf(ry, w1.w, fmaf(rx, w0.w, v.w))));
    }
    float4 o;
    if (p1 > p0) {
        o.x = lrelu(acc.x); o.y = lrelu(acc.y);
        o.z = lrelu(acc.z); o.w = lrelu(acc.w);
    } else {
        o = make_float4(0.f, 0.f, 0.f, 0.f);
    }
    *(float4*)&g_agg[(size_t)warp * 128 + c] = o;
}

// ---------------- fused: out = lrelu(agg@Wg1+bg1)@Wg2 + bg2 + x ----------------
__global__ __launch_bounds__(256, 1)
void gemm_out_kernel(const float* __restrict__ A, const float* __restrict__ B1,
                     const float* __restrict__ b1, const float* __restrict__ B2,
                     const float* __restrict__ b2, const float* __restrict__ X,
                     float* __restrict__ O, int M) {
    extern __shared__ float sm[];
    float* Bs1 = sm;                       // 16384
    float* Bs2 = sm + 16384;               // 16384
    float* Ts  = sm + 32768;               // 128*PADT = 16896
    float* As  = sm + 32768 + 16896;       // 16*PADA = 2176
    int tid = threadIdx.x, tx = tid & 15, ty = tid >> 4;
    int row0 = blockIdx.x * 128;

    #pragma unroll
    for (int it = 0; it < 16; ++it) {
        int idx = (it * 256 + tid) * 4;
        *(float4*)&Bs1[idx] = *(const float4*)&B1[idx];
        *(float4*)&Bs2[idx] = *(const float4*)&B2[idx];
    }
    unsigned long long acc[8][4];
    #pragma unroll
    for (int i = 0; i < 8; i++)
        #pragma unroll
        for (int j = 0; j < 4; j++) acc[i][j] = 0ull;

    gemm_core(A, M, row0, Bs1, As, acc, tid, tx, ty);

    // stage1 epilogue: bias + lrelu -> Ts
    {
        float4 bA = *(const float4*)&b1[tx * 4];
        float4 bB = *(const float4*)&b1[64 + tx * 4];
        #pragma unroll
        for (int i = 0; i < 8; i++) {
            int r = ty * 8 + i;
            float2 f0 = unpk(acc[i][0]), f1 = unpk(acc[i][1]);
            float2 f2 = unpk(acc[i][2]), f3 = unpk(acc[i][3]);
            float4 v0 = make_float4(lrelu(f0.x + bA.x), lrelu(f0.y + bA.y),
                                    lrelu(f1.x + bA.z), lrelu(f1.y + bA.w));
            float4 v1 = make_float4(lrelu(f2.x + bB.x), lrelu(f2.y + bB.y),
                                    lrelu(f3.x + bB.z), lrelu(f3.y + bB.w));
            *(float4*)&Ts[r * PADT + tx * 4]      = v0;
            *(float4*)&Ts[r * PADT + 64 + tx * 4] = v1;
        }
    }
    __syncthreads();

    // stage2: out = Ts @ Wg2
    #pragma unroll
    for (int i = 0; i < 8; i++)
        #pragma unroll
        for (int j = 0; j < 4; j++) acc[i][j] = 0ull;

    #pragma unroll 4
    for (int k = 0; k < 128; k++) {
        const float* br = &Bs2[k * 128];
        ulonglong2 b01 = *(const ulonglong2*)&br[tx * 4];
        ulonglong2 b23 = *(const ulonglong2*)&br[64 + tx * 4];
        #pragma unroll
        for (int i = 0; i < 8; i++) {
            unsigned long long as_ = splat2(Ts[(ty * 8 + i) * PADT + k]);
            fma2(acc[i][0], as_, b01.x);
            fma2(acc[i][1], as_, b01.y);
            fma2(acc[i][2], as_, b23.x);
            fma2(acc[i][3], as_, b23.y);
        }
    }

    float4 bA = *(const float4*)&b2[tx * 4];
    float4 bB = *(const float4*)&b2[64 + tx * 4];
    #pragma unroll
    for (int i = 0; i < 8; i++) {
        int grow = row0 + ty * 8 + i;
        if (grow >= M) continue;
        float2 f0 = unpk(acc[i][0]), f1 = unpk(acc[i][1]);
        float2 f2 = unpk(acc[i][2]), f3 = unpk(acc[i][3]);
        float4 r0 = *(const float4*)&X[(size_t)grow * 128 + tx * 4];
        float4 r1 = *(const float4*)&X[(size_t)grow * 128 + 64 + tx * 4];
        float4 o0 = make_float4(f0.x + bA.x + r0.x, f0.y + bA.y + r0.y,
                                f1.x + bA.z + r0.z, f1.y + bA.w + r0.w);
        float4 o1 = make_float4(f2.x + bB.x + r1.x, f2.y + bB.y + r1.y,
                                f3.x + bB.z + r1.z, f3.y + bB.w + r1.w);
        *(float4*)&O[(size_t)grow * 128 + tx * 4]      = o0;
        *(float4*)&O[(size_t)grow * 128 + 64 + tx * 4] = o1;
    }
}

// ---------------- launch ----------------
extern "C" void kernel_launch(void* const* d_in, const int* in_sizes, int n_in,
                              void* d_out, int out_size) {
    const float* x   = (const float*)d_in[0];
    const float* pos = (const float*)d_in[1];
    const void*  ei  = d_in[2];
    const float* Wh1 = (const float*)d_in[3];
    const float* bh1 = (const float*)d_in[4];
    const float* Wh2 = (const float*)d_in[5];
    const float* bh2 = (const float*)d_in[6];
    const float* Wf  = (const float*)d_in[7];
    const float* bf  = (const float*)d_in[8];
    const float* Wg1 = (const float*)d_in[9];
    const float* bg1 = (const float*)d_in[10];
    const float* Wg2 = (const float*)d_in[11];
    const float* bg2 = (const float*)d_in[12];
    float* out = (float*)d_out;

    int M = in_sizes[0] / CDIM;   // 50000
    int E = in_sizes[2] / 2;      // 800000

    const int SM_BIAS   = (16384 + 16 * PADA) * sizeof(float);
    const int SM_HDELTA = (16384 + 16 * PADA + 384 + 128 * 3) * sizeof(float);
    const int SM_OUT    = (16384 * 2 + 128 * PADT + 16 * PADA) * sizeof(float);
    cudaFuncSetAttribute(gemm_bias_kernel,   cudaFuncAttributeMaxDynamicSharedMemorySize, SM_BIAS);
    cudaFuncSetAttribute(gemm_hdelta_kernel, cudaFuncAttributeMaxDynamicSharedMemorySize, SM_HDELTA);
    cudaFuncSetAttribute(gemm_out_kernel,    cudaFuncAttributeMaxDynamicSharedMemorySize, SM_OUT);

    float *xfp, *aggp;
    cudaGetSymbolAddress((void**)&xfp,  g_xf);
    cudaGetSymbolAddress((void**)&aggp, g_agg);

    int gemm_blocks = (M + 127) / 128;
    int eblocks = (E + 255) / 256;
    int nblocks = (M + 255) / 256;
    int sblocks = (M + 1023) / 1024;
    int wblocks = (M + 7) / 8;

    static cudaStream_t s_side = nullptr;
    static cudaEvent_t  s_e0 = nullptr, s_e1 = nullptr;
    if (s_side == nullptr) {
        cudaStreamCreateWithFlags(&s_side, cudaStreamNonBlocking);
        cudaEventCreateWithFlags(&s_e0, cudaEventDisableTiming);
        cudaEventCreateWithFlags(&s_e1, cudaEventDisableTiming);
    }

    // fork: CSR build on side stream
    cudaEventRecord(s_e0, 0);
    cudaStreamWaitEvent(s_side, s_e0, 0);
    detect_kernel<<<1, 32, 0, s_side>>>((const unsigned int*)ei, E);
    zero_cnt_kernel<<<nblocks, 256, 0, s_side>>>(M);
    convert_hist_kernel<<<eblocks, 256, 0, s_side>>>(ei, E);
    scanA_kernel<<<sblocks, 1024, 0, s_side>>>(M);
    scanB_kernel<<<1, 64, 0, s_side>>>(sblocks);
    scanC_kernel<<<sblocks, 1024, 0, s_side>>>(M);
    scatter_kernel<<<eblocks, 256, 0, s_side>>>(E);
    cudaEventRecord(s_e1, s_side);

    // main stream: node GEMMs
    gemm_hdelta_kernel<<<gemm_blocks, 256, SM_HDELTA>>>(x, Wh1, bh1, Wh2, bh2, M);
    gemm_bias_kernel<<<gemm_blocks, 256, SM_BIAS>>>(x, Wf + 3 * 128, bf, xfp, M);

    // join, then aggregate + output MLP
    cudaStreamWaitEvent(0, s_e1, 0);
    agg_kernel<<<wblocks, 256>>>(pos, Wf, M);
    gemm_out_kernel<<<gemm_blocks, 256, SM_OUT>>>(aggp, Wg1, bg1, Wg2, bg2, x, out, M);
}